// round 10
// baseline (speedup 1.0000x reference)
#include <cuda_runtime.h>
#include <cuda_fp16.h>
#include <math.h>
#include <stdint.h>

#define Bq 128
#define Uq 256
#define NG 1280

// ---------------- scratch (static device globals) ----------------------------
__device__ float g_gsum[Bq * NG];
__device__ float g_c  [Bq * Uq];
__device__ float g_fre[Bq * Uq];
__device__ float g_ste[Bq * Uq];
__device__ float g_cos[Bq * Uq];
__device__ float g_sin[Bq * Uq];
__device__ __half g_Ah[(size_t)Uq * Bq * Uq];  // [k][b][u], 16.8MB
__device__ __half g_xh[Bq * Uq];
__device__ __half g_zh[Bq * Uq];

__device__ __forceinline__ float hsig(float v) {
    return fminf(fmaxf(0.2f * v + 0.5f, 0.0f), 1.0f);
}

// ---------------- PTX helpers (sm_80-level only) ------------------------------
__device__ __forceinline__ uint32_t smem_u32(const void* p) {
    uint32_t a;
    asm("{ .reg .u64 t; cvta.to.shared.u64 t, %1; cvt.u32.u64 %0, t; }" : "=r"(a) : "l"(p));
    return a;
}
__device__ __forceinline__ uint32_t packh(float lo, float hi) {
    __half2 h = __floats2half2_rn(lo, hi);
    return *(uint32_t*)&h;
}
__device__ __forceinline__ void sts128(uint32_t a, uint32_t r0, uint32_t r1, uint32_t r2, uint32_t r3) {
    asm volatile("st.shared.v4.b32 [%0], {%1,%2,%3,%4};"
                 :: "r"(a), "r"(r0), "r"(r1), "r"(r2), "r"(r3) : "memory");
}
__device__ __forceinline__ void cpa16(uint32_t dst, const void* src) {
    asm volatile("cp.async.cg.shared.global [%0], [%1], 16;" :: "r"(dst), "l"(src) : "memory");
}
__device__ __forceinline__ void cpa_commit() {
    asm volatile("cp.async.commit_group;" ::: "memory");
}
__device__ __forceinline__ void cpa_wait0() {
    asm volatile("cp.async.wait_group 0;" ::: "memory");
}
__device__ __forceinline__ void ldsm4(uint32_t* r, uint32_t addr) {
    asm volatile("ldmatrix.sync.aligned.m8n8.x4.shared.b16 {%0,%1,%2,%3}, [%4];"
                 : "=r"(r[0]), "=r"(r[1]), "=r"(r[2]), "=r"(r[3]) : "r"(addr));
}
__device__ __forceinline__ void ldsm4t(uint32_t* r, uint32_t addr) {
    asm volatile("ldmatrix.sync.aligned.m8n8.x4.trans.shared.b16 {%0,%1,%2,%3}, [%4];"
                 : "=r"(r[0]), "=r"(r[1]), "=r"(r[2]), "=r"(r[3]) : "r"(addr));
}
__device__ __forceinline__ void mma_f16(float* c, const uint32_t* a, const uint32_t* b) {
    asm volatile(
        "mma.sync.aligned.m16n8k16.row.col.f32.f16.f16.f32 "
        "{%0,%1,%2,%3}, {%4,%5,%6,%7}, {%8,%9}, {%0,%1,%2,%3};"
        : "+f"(c[0]), "+f"(c[1]), "+f"(c[2]), "+f"(c[3])
        : "r"(a[0]), "r"(a[1]), "r"(a[2]), "r"(a[3]), "r"(b[0]), "r"(b[1]));
}

// ============================================================================
// Kernel 1: g_gsum = x @ kernel + z_prev @ recur_k + bias.  32x64 tiles.
// ============================================================================
__global__ __launch_bounds__(256) void k_gates_gemm(
    const float* __restrict__ x, const float* __restrict__ z_prev,
    const float* __restrict__ kern, const float* __restrict__ recur,
    const float* __restrict__ bias)
{
    __shared__ float sX[32][33];
    __shared__ float sW[32][68];
    const int tid = threadIdx.x;
    const int j0 = blockIdx.x * 64, b0 = blockIdx.y * 32;
    const int rg = tid >> 4, cg = tid & 15;
    float acc[2][4];
#pragma unroll
    for (int i = 0; i < 2; i++)
#pragma unroll
        for (int j = 0; j < 4; j++) acc[i][j] = 0.f;

#pragma unroll
    for (int pass = 0; pass < 2; pass++) {
        const float* L = pass ? z_prev : x;
        const float* W = pass ? recur : kern;
        for (int d0 = 0; d0 < 256; d0 += 32) {
            {
                const int lb = tid >> 3, lu = (tid & 7) * 4;
                float4 v = *(const float4*)&L[(b0 + lb) * 256 + d0 + lu];
                sX[lu][lb] = v.x; sX[lu + 1][lb] = v.y;
                sX[lu + 2][lb] = v.z; sX[lu + 3][lb] = v.w;
            }
#pragma unroll
            for (int i2 = 0; i2 < 2; i2++) {
                const int wu = (tid >> 4) + i2 * 16, wc = (tid & 15) * 4;
                *(float4*)&sW[wu][wc] = *(const float4*)&W[(d0 + wu) * NG + j0 + wc];
            }
            __syncthreads();
#pragma unroll
            for (int kk = 0; kk < 32; kk++) {
                float a0 = sX[kk][rg * 2], a1 = sX[kk][rg * 2 + 1];
                float bb[4];
#pragma unroll
                for (int j = 0; j < 4; j++) bb[j] = sW[kk][cg * 4 + j];
#pragma unroll
                for (int j = 0; j < 4; j++) { acc[0][j] += a0 * bb[j]; acc[1][j] += a1 * bb[j]; }
            }
            __syncthreads();
        }
    }
#pragma unroll
    for (int i = 0; i < 2; i++) {
        const int b = b0 + rg * 2 + i;
#pragma unroll
        for (int j = 0; j < 4; j++) {
            const int jj = j0 + cg * 4 + j;
            g_gsum[b * NG + jj] = acc[i][j] + bias[jj];
        }
    }
}

// ============================================================================
// Kernel 2: elementwise gates + omega out + cos/sin + fp16 copies of x, z_prev
// ============================================================================
__global__ __launch_bounds__(256) void k_gates_ew(
    const float* __restrict__ x, const float* __restrict__ z_prev,
    const float* __restrict__ omg_prev, const float* __restrict__ t,
    float* __restrict__ out_omg)
{
    const int idx = blockIdx.x * blockDim.x + threadIdx.x;
    const int b = idx >> 8, u = idx & 255;
    const float* g = &g_gsum[b * NG];
    const float i_g = hsig(g[u]);
    const float fre = hsig(g[Uq + u]);
    const float ste = hsig(g[2 * Uq + u]);
    const float gg  = tanhf(g[3 * Uq + u]);
    g_c[idx] = i_g * gg; g_fre[idx] = fre; g_ste[idx] = ste;
    const float th = omg_prev[idx] * t[b];
    g_cos[idx] = cosf(th); g_sin[idx] = sinf(th);
    out_omg[idx] = g[4 * Uq + u];
    g_xh[idx] = __float2half_rn(x[idx]);
    g_zh[idx] = __float2half_rn(z_prev[idx]);
}

// ============================================================================
// Kernel 3: Re/Im update + A = sqrt(Re^2+Im^2) -> g_Ah [k][b][u] (fp16)
// ============================================================================
__global__ __launch_bounds__(256) void k_reim(
    const float* __restrict__ Re_prev, const float* __restrict__ Im_prev,
    float* __restrict__ Im_out, float* __restrict__ Re_out)
{
    __shared__ float sA[64][65];
    const int b = blockIdx.z, i0 = blockIdx.y * 64, j0 = blockIdx.x * 64;
    const int t16 = threadIdx.x & 15, tr = threadIdx.x >> 4;
    const int j4 = t16 * 4;

    const float4 fre4 = *(const float4*)&g_fre[b * Uq + j0 + j4];
    const float4 cos4 = *(const float4*)&g_cos[b * Uq + j0 + j4];
    const float4 sin4 = *(const float4*)&g_sin[b * Uq + j0 + j4];
    const float frev[4] = {fre4.x, fre4.y, fre4.z, fre4.w};
    const float cosv[4] = {cos4.x, cos4.y, cos4.z, cos4.w};
    const float sinv[4] = {sin4.x, sin4.y, sin4.z, sin4.w};

#pragma unroll
    for (int r = 0; r < 4; r++) {
        const int i = tr + r * 16;
        const float ste_i = g_ste[b * Uq + i0 + i];
        const float ci    = g_c  [b * Uq + i0 + i];
        const size_t idx = ((size_t)b * Uq + (i0 + i)) * Uq + j0 + j4;
        const float4 rp = *(const float4*)&Re_prev[idx];
        const float4 ip = *(const float4*)&Im_prev[idx];
        const float rpv[4] = {rp.x, rp.y, rp.z, rp.w};
        const float ipv[4] = {ip.x, ip.y, ip.z, ip.w};
        float rev[4], imv[4];
#pragma unroll
        for (int q = 0; q < 4; q++) {
            const float f = ste_i * frev[q];
            rev[q] = f * rpv[q] + ci * cosv[q];
            imv[q] = f * ipv[q] + ci * sinv[q];
            sA[i][j4 + q] = sqrtf(rev[q] * rev[q] + imv[q] * imv[q]);
        }
        *(float4*)&Re_out[idx] = make_float4(rev[0], rev[1], rev[2], rev[3]);
        *(float4*)&Im_out[idx] = make_float4(imv[0], imv[1], imv[2], imv[3]);
    }
    __syncthreads();
#pragma unroll
    for (int r = 0; r < 4; r++) {
        const int j = tr + r * 16;
        const int i4 = t16 * 4;
        __half2 h0 = __floats2half2_rn(sA[i4][j],     sA[i4 + 1][j]);
        __half2 h1 = __floats2half2_rn(sA[i4 + 2][j], sA[i4 + 3][j]);
        uint2 v = make_uint2(*(uint32_t*)&h0, *(uint32_t*)&h1);
        *(uint2*)&g_Ah[((size_t)(j0 + j) * 128 + b) * 256 + i0 + i4] = v;
    }
}

// ============================================================================
// Kernel 4: per-k fused GEMMs via mma.sync fp16 -- uniform 8-iteration loop.
// Grid (4 vq, 256 k). 256 threads, warps 4(M)x2(N), warp tile 32x32.
// it 0-3 (A):  LHS=A chunk it      B0=U_o, B1=W_z   -> acc_o, acc_z
// it 4-5 (x):  LHS=x chunks {2j,2j+1}  B0,B1 = W_o halves -> acc_o
// it 6-7 (z):  LHS=z chunks {2j,2j+1}  B0,B1 = V_o halves -> acc_o
// Every iteration: 32KB of B via LDG->cvt->STS, LHS via cp.async, 64 HMMA/warp.
// ============================================================================
#define LDA 144                 // 64 fp16 (128B) + 16B pad
#define LDB 144
#define L_BYTES (128*LDA)       // 18432 per LHS slot
#define B_BYTES (64*LDB)        // 9216
#define OFF_B0 (2*L_BYTES)      // 36864
#define OFF_B1 (OFF_B0 + B_BYTES)
#define STG (2*L_BYTES + 2*B_BYTES)   // 55296
#define SMEM_TOT (2*STG)              // 110592

__global__ __launch_bounds__(256, 2) void k_freq_mma(
    const float* __restrict__ freq_k, const float* __restrict__ freq_ki,
    const float* __restrict__ freqb, float* __restrict__ z_out)
{
    extern __shared__ char smem[];
    const uint32_t sbase = smem_u32(smem);
    const int tid = threadIdx.x, l = tid & 31, w = tid >> 5;
    const int wm = w & 3, wn = w >> 2;
    const int k = blockIdx.y, v0 = blockIdx.x * 64;

    float acc_o[2][4][4], acc_z[2][4][4];
#pragma unroll
    for (int i = 0; i < 32; i++) { ((float*)acc_o)[i] = 0.f; ((float*)acc_z)[i] = 0.f; }

    const uint32_t a_base = (uint32_t)((wm * 32 + (l & 15)) * LDA + (l >> 4) * 16);
    const uint32_t b_base = (uint32_t)((l & 15) * LDB + wn * 64 + (l >> 4) * 16);

    float4 hb[8];

    auto load_lhs = [&](int it, int buf) {
        const uint32_t dst = sbase + buf * STG;
        if (it < 4) {
            const __half* ls = g_Ah + (size_t)k * 32768 + it * 64;
#pragma unroll
            for (int i = 0; i < 4; i++) {
                const int idx = tid + i * 256;
                const int row = idx >> 3, g = idx & 7;
                cpa16(dst + row * LDA + g * 16, ls + row * 256 + g * 8);
            }
        } else {
            const __half* base = (it < 6) ? g_xh : g_zh;
            const int c0 = (it & 1) * 2;
            const __half* ls0 = base + c0 * 64;
            const __half* ls1 = base + (c0 + 1) * 64;
#pragma unroll
            for (int i = 0; i < 4; i++) {
                const int idx = tid + i * 256;
                const int row = idx >> 3, g = idx & 7;
                cpa16(dst + row * LDA + g * 16, ls0 + row * 256 + g * 8);
                cpa16(dst + L_BYTES + row * LDA + g * 16, ls1 + row * 256 + g * 8);
            }
        }
        cpa_commit();
    };

    auto load_b_regs = [&](int it) {
        const float *b0, *b1; int st;
        if (it < 4) {
            st = 768;
            b0 = freq_k + (size_t)k * 196608 + (size_t)(it * 64) * 768 + v0;        // U_o
            b1 = freq_k + (size_t)k * 196608 + (size_t)(it * 64) * 768 + 512 + v0;  // W_z
        } else if (it < 6) {
            st = 256;
            const int c0 = (it & 1) * 2;
            b0 = freq_ki + (size_t)k * 65536 + (size_t)(c0 * 64) * 256 + v0;        // W_o
            b1 = freq_ki + (size_t)k * 65536 + (size_t)((c0 + 1) * 64) * 256 + v0;
        } else {
            st = 768;
            const int c0 = (it & 1) * 2;
            b0 = freq_k + (size_t)k * 196608 + (size_t)(c0 * 64) * 768 + 256 + v0;  // V_o
            b1 = freq_k + (size_t)k * 196608 + (size_t)((c0 + 1) * 64) * 768 + 256 + v0;
        }
#pragma unroll
        for (int i = 0; i < 2; i++) {
            const int idx = tid + i * 256;
            const int r = idx >> 3, g = idx & 7;
            hb[2 * i]     = __ldg((const float4*)(b0 + (size_t)r * st + g * 8));
            hb[2 * i + 1] = __ldg((const float4*)(b0 + (size_t)r * st + g * 8 + 4));
            hb[4 + 2 * i] = __ldg((const float4*)(b1 + (size_t)r * st + g * 8));
            hb[5 + 2 * i] = __ldg((const float4*)(b1 + (size_t)r * st + g * 8 + 4));
        }
    };

    auto store_b = [&](int buf) {
        const uint32_t sB0 = sbase + buf * STG + OFF_B0;
        const uint32_t sB1 = sbase + buf * STG + OFF_B1;
#pragma unroll
        for (int i = 0; i < 2; i++) {
            const int idx = tid + i * 256;
            const int r = idx >> 3, g = idx & 7;
            sts128(sB0 + r * LDB + g * 16,
                   packh(hb[2 * i].x, hb[2 * i].y), packh(hb[2 * i].z, hb[2 * i].w),
                   packh(hb[2 * i + 1].x, hb[2 * i + 1].y), packh(hb[2 * i + 1].z, hb[2 * i + 1].w));
            sts128(sB1 + r * LDB + g * 16,
                   packh(hb[4 + 2 * i].x, hb[4 + 2 * i].y), packh(hb[4 + 2 * i].z, hb[4 + 2 * i].w),
                   packh(hb[5 + 2 * i].x, hb[5 + 2 * i].y), packh(hb[5 + 2 * i].z, hb[5 + 2 * i].w));
        }
    };

    // ---- prologue ----------------------------------------------------------
    load_lhs(0, 0);
    load_b_regs(0);

#pragma unroll 1
    for (int it = 0; it < 8; it++) {
        const int buf = it & 1;
        store_b(buf);
        cpa_wait0();
        __syncthreads();

        if (it < 7) {
            load_lhs(it + 1, buf ^ 1);
            load_b_regs(it + 1);
        }

        const uint32_t sL0 = sbase + buf * STG;
        const uint32_t sL1 = sL0 + L_BYTES;
        const uint32_t sB0 = sL0 + OFF_B0;
        const uint32_t sB1 = sL0 + OFF_B1;

        if (it < 4) {
            // dual: acc_o += A x B0 ; acc_z += A x B1
#pragma unroll
            for (int s = 0; s < 4; s++) {
                uint32_t af[2][4], bf[2][4], bz[2][4];
                ldsm4(af[0], sL0 + a_base + s * 32);
                ldsm4(af[1], sL0 + a_base + 16 * LDA + s * 32);
#pragma unroll
                for (int nt = 0; nt < 2; nt++) {
                    ldsm4t(bf[nt], sB0 + b_base + s * 16 * LDB + nt * 32);
                    ldsm4t(bz[nt], sB1 + b_base + s * 16 * LDB + nt * 32);
                }
#pragma unroll
                for (int mt = 0; mt < 2; mt++)
#pragma unroll
                    for (int nt = 0; nt < 2; nt++) {
                        mma_f16(acc_o[mt][2 * nt],     af[mt], &bf[nt][0]);
                        mma_f16(acc_o[mt][2 * nt + 1], af[mt], &bf[nt][2]);
                        mma_f16(acc_z[mt][2 * nt],     af[mt], &bz[nt][0]);
                        mma_f16(acc_z[mt][2 * nt + 1], af[mt], &bz[nt][2]);
                    }
            }
        } else {
            // two K64 sub-chunks, acc_o only
#pragma unroll
            for (int h = 0; h < 2; h++) {
                const uint32_t sL = h ? sL1 : sL0;
                const uint32_t sB = h ? sB1 : sB0;
#pragma unroll
                for (int s = 0; s < 4; s++) {
                    uint32_t af[2][4], bf[2][4];
                    ldsm4(af[0], sL + a_base + s * 32);
                    ldsm4(af[1], sL + a_base + 16 * LDA + s * 32);
#pragma unroll
                    for (int nt = 0; nt < 2; nt++)
                        ldsm4t(bf[nt], sB + b_base + s * 16 * LDB + nt * 32);
#pragma unroll
                    for (int mt = 0; mt < 2; mt++)
#pragma unroll
                        for (int nt = 0; nt < 2; nt++) {
                            mma_f16(acc_o[mt][2 * nt],     af[mt], &bf[nt][0]);
                            mma_f16(acc_o[mt][2 * nt + 1], af[mt], &bf[nt][2]);
                        }
                }
            }
        }
    }

    // ---- epilogue: zz = hsig(C_o + b_o) * tanh(C_z + b_z); z += zz ----------
    const float* bo = freqb + (size_t)k * 256;
    const float* bz = freqb + (size_t)(256 + k) * 256;
#pragma unroll
    for (int mt = 0; mt < 2; mt++)
#pragma unroll
        for (int j = 0; j < 4; j++)
#pragma unroll
            for (int r = 0; r < 4; r++) {
                const int b = wm * 32 + mt * 16 + (l >> 2) + (r >> 1) * 8;
                const int v = v0 + wn * 32 + j * 8 + (l & 3) * 2 + (r & 1);
                const float o = hsig(acc_o[mt][j][r] + __ldg(bo + v));
                const float zz = o * tanhf(acc_z[mt][j][r] + __ldg(bz + v));
                atomicAdd(&z_out[b * 256 + v], zz);
            }
}

// ============================================================================
// launch
// ============================================================================
extern "C" void kernel_launch(void* const* d_in, const int* in_sizes, int n_in,
                              void* d_out, int out_size)
{
    const float* x        = (const float*)d_in[0];
    const float* t        = (const float*)d_in[1];
    const float* z_prev   = (const float*)d_in[2];
    const float* Im_prev  = (const float*)d_in[3];
    const float* Re_prev  = (const float*)d_in[4];
    const float* omg_prev = (const float*)d_in[5];
    const float* kern     = (const float*)d_in[6];
    const float* recur    = (const float*)d_in[7];
    const float* freq_k   = (const float*)d_in[8];
    const float* freq_ki  = (const float*)d_in[9];
    const float* bias     = (const float*)d_in[10];
    const float* freqb    = (const float*)d_in[11];

    float* out     = (float*)d_out;
    float* z_out   = out;
    float* im_out  = out + 32768;
    float* re_out  = out + 32768 + 8388608;
    float* omg_out = out + 32768 + 2 * 8388608;

    static int smem_set = 0;
    if (!smem_set) {
        cudaFuncSetAttribute(k_freq_mma, cudaFuncAttributeMaxDynamicSharedMemorySize, SMEM_TOT);
        smem_set = 1;
    }

    cudaMemsetAsync(z_out, 0, 32768 * sizeof(float), 0);
    k_gates_gemm<<<dim3(20, 4), 256>>>(x, z_prev, kern, recur, bias);
    k_gates_ew<<<128, 256>>>(x, z_prev, omg_prev, t, omg_out);
    k_reim<<<dim3(4, 4, 128), 256>>>(Re_prev, Im_prev, im_out, re_out);
    k_freq_mma<<<dim3(4, 256), 256, SMEM_TOT>>>(freq_k, freq_ki, freqb, z_out);
}

// round 11
// speedup vs baseline: 1.0983x; 1.0983x over previous
#include <cuda_runtime.h>
#include <cuda_fp16.h>
#include <math.h>
#include <stdint.h>

#define Bq 128
#define Uq 256
#define NG 1280

// ---------------- scratch (static device globals) ----------------------------
__device__ float g_gsum[Bq * NG];
__device__ float g_c  [Bq * Uq];
__device__ float g_fre[Bq * Uq];
__device__ float g_ste[Bq * Uq];
__device__ float g_cos[Bq * Uq];
__device__ float g_sin[Bq * Uq];
__device__ __half g_Ah[(size_t)Uq * Bq * Uq];  // [k][b][u], 16.8MB
__device__ __half g_xh[Bq * Uq];
__device__ __half g_zh[Bq * Uq];

__device__ __forceinline__ float hsig(float v) {
    return fminf(fmaxf(0.2f * v + 0.5f, 0.0f), 1.0f);
}

// ---------------- PTX helpers (sm_80-level only) ------------------------------
__device__ __forceinline__ uint32_t smem_u32(const void* p) {
    uint32_t a;
    asm("{ .reg .u64 t; cvta.to.shared.u64 t, %1; cvt.u32.u64 %0, t; }" : "=r"(a) : "l"(p));
    return a;
}
__device__ __forceinline__ uint32_t packh(float lo, float hi) {
    __half2 h = __floats2half2_rn(lo, hi);
    return *(uint32_t*)&h;
}
__device__ __forceinline__ void sts128(uint32_t a, uint32_t r0, uint32_t r1, uint32_t r2, uint32_t r3) {
    asm volatile("st.shared.v4.b32 [%0], {%1,%2,%3,%4};"
                 :: "r"(a), "r"(r0), "r"(r1), "r"(r2), "r"(r3) : "memory");
}
__device__ __forceinline__ void cpa16(uint32_t dst, const void* src) {
    asm volatile("cp.async.cg.shared.global [%0], [%1], 16;" :: "r"(dst), "l"(src) : "memory");
}
__device__ __forceinline__ void cpa_commit() {
    asm volatile("cp.async.commit_group;" ::: "memory");
}
__device__ __forceinline__ void cpa_wait0() {
    asm volatile("cp.async.wait_group 0;" ::: "memory");
}
__device__ __forceinline__ void cpa_wait1() {
    asm volatile("cp.async.wait_group 1;" ::: "memory");
}
__device__ __forceinline__ void ldsm4(uint32_t* r, uint32_t addr) {
    asm volatile("ldmatrix.sync.aligned.m8n8.x4.shared.b16 {%0,%1,%2,%3}, [%4];"
                 : "=r"(r[0]), "=r"(r[1]), "=r"(r[2]), "=r"(r[3]) : "r"(addr));
}
__device__ __forceinline__ void ldsm4t(uint32_t* r, uint32_t addr) {
    asm volatile("ldmatrix.sync.aligned.m8n8.x4.trans.shared.b16 {%0,%1,%2,%3}, [%4];"
                 : "=r"(r[0]), "=r"(r[1]), "=r"(r[2]), "=r"(r[3]) : "r"(addr));
}
__device__ __forceinline__ void mma_f16(float* c, const uint32_t* a, const uint32_t* b) {
    asm volatile(
        "mma.sync.aligned.m16n8k16.row.col.f32.f16.f16.f32 "
        "{%0,%1,%2,%3}, {%4,%5,%6,%7}, {%8,%9}, {%0,%1,%2,%3};"
        : "+f"(c[0]), "+f"(c[1]), "+f"(c[2]), "+f"(c[3])
        : "r"(a[0]), "r"(a[1]), "r"(a[2]), "r"(a[3]), "r"(b[0]), "r"(b[1]));
}

// ============================================================================
// Kernel 1: g_gsum = x @ kernel + z_prev @ recur_k + bias.  32x64 tiles.
// ============================================================================
__global__ __launch_bounds__(256) void k_gates_gemm(
    const float* __restrict__ x, const float* __restrict__ z_prev,
    const float* __restrict__ kern, const float* __restrict__ recur,
    const float* __restrict__ bias)
{
    __shared__ float sX[32][33];
    __shared__ float sW[32][68];
    const int tid = threadIdx.x;
    const int j0 = blockIdx.x * 64, b0 = blockIdx.y * 32;
    const int rg = tid >> 4, cg = tid & 15;
    float acc[2][4];
#pragma unroll
    for (int i = 0; i < 2; i++)
#pragma unroll
        for (int j = 0; j < 4; j++) acc[i][j] = 0.f;

#pragma unroll
    for (int pass = 0; pass < 2; pass++) {
        const float* L = pass ? z_prev : x;
        const float* W = pass ? recur : kern;
        for (int d0 = 0; d0 < 256; d0 += 32) {
            {
                const int lb = tid >> 3, lu = (tid & 7) * 4;
                float4 v = *(const float4*)&L[(b0 + lb) * 256 + d0 + lu];
                sX[lu][lb] = v.x; sX[lu + 1][lb] = v.y;
                sX[lu + 2][lb] = v.z; sX[lu + 3][lb] = v.w;
            }
#pragma unroll
            for (int i2 = 0; i2 < 2; i2++) {
                const int wu = (tid >> 4) + i2 * 16, wc = (tid & 15) * 4;
                *(float4*)&sW[wu][wc] = *(const float4*)&W[(d0 + wu) * NG + j0 + wc];
            }
            __syncthreads();
#pragma unroll
            for (int kk = 0; kk < 32; kk++) {
                float a0 = sX[kk][rg * 2], a1 = sX[kk][rg * 2 + 1];
                float bb[4];
#pragma unroll
                for (int j = 0; j < 4; j++) bb[j] = sW[kk][cg * 4 + j];
#pragma unroll
                for (int j = 0; j < 4; j++) { acc[0][j] += a0 * bb[j]; acc[1][j] += a1 * bb[j]; }
            }
            __syncthreads();
        }
    }
#pragma unroll
    for (int i = 0; i < 2; i++) {
        const int b = b0 + rg * 2 + i;
#pragma unroll
        for (int j = 0; j < 4; j++) {
            const int jj = j0 + cg * 4 + j;
            g_gsum[b * NG + jj] = acc[i][j] + bias[jj];
        }
    }
}

// ============================================================================
// Kernel 2: elementwise gates + omega out + cos/sin + fp16 copies of x, z_prev
// ============================================================================
__global__ __launch_bounds__(256) void k_gates_ew(
    const float* __restrict__ x, const float* __restrict__ z_prev,
    const float* __restrict__ omg_prev, const float* __restrict__ t,
    float* __restrict__ out_omg)
{
    const int idx = blockIdx.x * blockDim.x + threadIdx.x;
    const int b = idx >> 8, u = idx & 255;
    const float* g = &g_gsum[b * NG];
    const float i_g = hsig(g[u]);
    const float fre = hsig(g[Uq + u]);
    const float ste = hsig(g[2 * Uq + u]);
    const float gg  = tanhf(g[3 * Uq + u]);
    g_c[idx] = i_g * gg; g_fre[idx] = fre; g_ste[idx] = ste;
    const float th = omg_prev[idx] * t[b];
    g_cos[idx] = cosf(th); g_sin[idx] = sinf(th);
    out_omg[idx] = g[4 * Uq + u];
    g_xh[idx] = __float2half_rn(x[idx]);
    g_zh[idx] = __float2half_rn(z_prev[idx]);
}

// ============================================================================
// Kernel 3: Re/Im update + A = sqrt(Re^2+Im^2) -> g_Ah [k][b][u] (fp16)
// ============================================================================
__global__ __launch_bounds__(256) void k_reim(
    const float* __restrict__ Re_prev, const float* __restrict__ Im_prev,
    float* __restrict__ Im_out, float* __restrict__ Re_out)
{
    __shared__ float sA[64][65];
    const int b = blockIdx.z, i0 = blockIdx.y * 64, j0 = blockIdx.x * 64;
    const int t16 = threadIdx.x & 15, tr = threadIdx.x >> 4;
    const int j4 = t16 * 4;

    const float4 fre4 = *(const float4*)&g_fre[b * Uq + j0 + j4];
    const float4 cos4 = *(const float4*)&g_cos[b * Uq + j0 + j4];
    const float4 sin4 = *(const float4*)&g_sin[b * Uq + j0 + j4];
    const float frev[4] = {fre4.x, fre4.y, fre4.z, fre4.w};
    const float cosv[4] = {cos4.x, cos4.y, cos4.z, cos4.w};
    const float sinv[4] = {sin4.x, sin4.y, sin4.z, sin4.w};

#pragma unroll
    for (int r = 0; r < 4; r++) {
        const int i = tr + r * 16;
        const float ste_i = g_ste[b * Uq + i0 + i];
        const float ci    = g_c  [b * Uq + i0 + i];
        const size_t idx = ((size_t)b * Uq + (i0 + i)) * Uq + j0 + j4;
        const float4 rp = *(const float4*)&Re_prev[idx];
        const float4 ip = *(const float4*)&Im_prev[idx];
        const float rpv[4] = {rp.x, rp.y, rp.z, rp.w};
        const float ipv[4] = {ip.x, ip.y, ip.z, ip.w};
        float rev[4], imv[4];
#pragma unroll
        for (int q = 0; q < 4; q++) {
            const float f = ste_i * frev[q];
            rev[q] = f * rpv[q] + ci * cosv[q];
            imv[q] = f * ipv[q] + ci * sinv[q];
            sA[i][j4 + q] = sqrtf(rev[q] * rev[q] + imv[q] * imv[q]);
        }
        *(float4*)&Re_out[idx] = make_float4(rev[0], rev[1], rev[2], rev[3]);
        *(float4*)&Im_out[idx] = make_float4(imv[0], imv[1], imv[2], imv[3]);
    }
    __syncthreads();
#pragma unroll
    for (int r = 0; r < 4; r++) {
        const int j = tr + r * 16;
        const int i4 = t16 * 4;
        __half2 h0 = __floats2half2_rn(sA[i4][j],     sA[i4 + 1][j]);
        __half2 h1 = __floats2half2_rn(sA[i4 + 2][j], sA[i4 + 3][j]);
        uint2 v = make_uint2(*(uint32_t*)&h0, *(uint32_t*)&h1);
        *(uint2*)&g_Ah[((size_t)(j0 + j) * 128 + b) * 256 + i0 + i4] = v;
    }
}

// ============================================================================
// Kernel 4: per-k fused GEMMs via mma.sync fp16 -- R9 12-chunk structure with
// prefetch-distance-2 software pipeline (3 LHS slots, 2 B slots).
// Grid (4 vq, 256 k). 256 threads, warps 4(M)x2(N), warp tile 32x32.
// Chunks of K=64:  c 0-3:  A @ [U_o | W_z]  -> acc_o, acc_z
//                  c 4-7:  x @ W_o          -> acc_o
//                  c 8-11: z_prev @ V_o     -> acc_o
// Iteration c: MMA(c) runs while store_b(c+1) (STS) and loads for c+2
// (cp.async LHS + LDG B) are issued -- conversion is off the critical path.
// ============================================================================
#define LDA 144                 // 64 fp16 (128B) + 16B pad
#define LDB 144
#define L_BYTES (128*LDA)       // 18432 per LHS slot
#define B_BYTES (64*LDB)        // 9216 per B tile
#define BP_BYTES (2*B_BYTES)    // 18432 per B pair slot
#define SMEM_TOT (3*L_BYTES + 2*BP_BYTES)   // 92160

__global__ __launch_bounds__(256, 2) void k_freq_mma(
    const float* __restrict__ freq_k, const float* __restrict__ freq_ki,
    const float* __restrict__ freqb, float* __restrict__ z_out)
{
    extern __shared__ char smem[];
    const uint32_t sbase = smem_u32(smem);
    const int tid = threadIdx.x, l = tid & 31, w = tid >> 5;
    const int wm = w & 3, wn = w >> 2;
    const int k = blockIdx.y, v0 = blockIdx.x * 64;

    const uint32_t L0 = sbase, L1 = sbase + L_BYTES, L2 = sbase + 2 * L_BYTES;
    const uint32_t P0 = sbase + 3 * L_BYTES, P1 = P0 + BP_BYTES;

    float acc_o[2][4][4], acc_z[2][4][4];
#pragma unroll
    for (int i = 0; i < 32; i++) { ((float*)acc_o)[i] = 0.f; ((float*)acc_z)[i] = 0.f; }

    const uint32_t a_base = (uint32_t)((wm * 32 + (l & 15)) * LDA + (l >> 4) * 16);
    const uint32_t b_base = (uint32_t)((l & 15) * LDB + wn * 64 + (l >> 4) * 16);

    float4 hb[8];

    auto load_lhs = [&](int c, uint32_t dst) {
        const __half* ls;
        if (c < 4)      ls = g_Ah + (size_t)k * 32768 + c * 64;
        else if (c < 8) ls = g_xh + (c - 4) * 64;
        else            ls = g_zh + (c - 8) * 64;
#pragma unroll
        for (int i = 0; i < 4; i++) {
            const int idx = tid + i * 256;
            const int row = idx >> 3, g = idx & 7;
            cpa16(dst + row * LDA + g * 16, ls + row * 256 + g * 8);
        }
        cpa_commit();
    };
    auto load_b_regs = [&](int c) {
        const float* b0; int st;
        if (c < 4)      { st = 768; b0 = freq_k  + (size_t)k * 196608 + (size_t)c * 64 * 768 + v0; }
        else if (c < 8) { st = 256; b0 = freq_ki + (size_t)k * 65536  + (size_t)(c - 4) * 64 * 256 + v0; }
        else            { st = 768; b0 = freq_k  + (size_t)k * 196608 + (size_t)(c - 8) * 64 * 768 + 256 + v0; }
#pragma unroll
        for (int i = 0; i < 2; i++) {
            const int idx = tid + i * 256;
            const int r = idx >> 3, g = idx & 7;
            hb[2 * i]     = __ldg((const float4*)(b0 + (size_t)r * st + g * 8));
            hb[2 * i + 1] = __ldg((const float4*)(b0 + (size_t)r * st + g * 8 + 4));
        }
        if (c < 4) {
            const float* b1 = freq_k + (size_t)k * 196608 + (size_t)c * 64 * 768 + 512 + v0;
#pragma unroll
            for (int i = 0; i < 2; i++) {
                const int idx = tid + i * 256;
                const int r = idx >> 3, g = idx & 7;
                hb[4 + 2 * i] = __ldg((const float4*)(b1 + (size_t)r * 768 + g * 8));
                hb[5 + 2 * i] = __ldg((const float4*)(b1 + (size_t)r * 768 + g * 8 + 4));
            }
        }
    };
    auto store_b = [&](int c, uint32_t bp) {
#pragma unroll
        for (int i = 0; i < 2; i++) {
            const int idx = tid + i * 256;
            const int r = idx >> 3, g = idx & 7;
            sts128(bp + r * LDB + g * 16,
                   packh(hb[2 * i].x, hb[2 * i].y), packh(hb[2 * i].z, hb[2 * i].w),
                   packh(hb[2 * i + 1].x, hb[2 * i + 1].y), packh(hb[2 * i + 1].z, hb[2 * i + 1].w));
        }
        if (c < 4) {
#pragma unroll
            for (int i = 0; i < 2; i++) {
                const int idx = tid + i * 256;
                const int r = idx >> 3, g = idx & 7;
                sts128(bp + B_BYTES + r * LDB + g * 16,
                       packh(hb[4 + 2 * i].x, hb[4 + 2 * i].y), packh(hb[4 + 2 * i].z, hb[4 + 2 * i].w),
                       packh(hb[5 + 2 * i].x, hb[5 + 2 * i].y), packh(hb[5 + 2 * i].z, hb[5 + 2 * i].w));
            }
        }
    };

    // ---- prologue: LHS(0),LHS(1) in flight; B(0) converted; B(1) in regs ----
    load_lhs(0, L0);
    load_lhs(1, L1);
    load_b_regs(0);
    store_b(0, P0);
    load_b_regs(1);
    cpa_wait1();          // LHS(0) complete
    __syncthreads();

    uint32_t sL = L0;     // LHS slot for current c (rotates L0->L1->L2)
    int lhs_next = 2;     // which slot index load_lhs(c+2) targets: (c+2)%3

#pragma unroll 1
    for (int c = 0; c < 12; c++) {
        const uint32_t sB0 = (c & 1) ? P1 : P0;
        const uint32_t sB1 = sB0 + B_BYTES;
        const uint32_t sBn = (c & 1) ? P0 : P1;

        // off-critical-path work: convert B(c+1), launch loads for c+2
        if (c < 11) store_b(c + 1, sBn);
        if (c < 10) {
            const uint32_t dst = (lhs_next == 0) ? L0 : (lhs_next == 1) ? L1 : L2;
            load_lhs(c + 2, dst);
            load_b_regs(c + 2);
            lhs_next = (lhs_next == 2) ? 0 : lhs_next + 1;
        }

        // MMA over chunk c (reads sL + sB0/sB1, all ready since last sync)
        if (c < 4) {
#pragma unroll
            for (int s = 0; s < 4; s++) {
                uint32_t af[2][4], bf[2][4], bz[2][4];
                ldsm4(af[0], sL + a_base + s * 32);
                ldsm4(af[1], sL + a_base + 16 * LDA + s * 32);
#pragma unroll
                for (int nt = 0; nt < 2; nt++) {
                    ldsm4t(bf[nt], sB0 + b_base + s * 16 * LDB + nt * 32);
                    ldsm4t(bz[nt], sB1 + b_base + s * 16 * LDB + nt * 32);
                }
#pragma unroll
                for (int mt = 0; mt < 2; mt++)
#pragma unroll
                    for (int nt = 0; nt < 2; nt++) {
                        mma_f16(acc_o[mt][2 * nt],     af[mt], &bf[nt][0]);
                        mma_f16(acc_o[mt][2 * nt + 1], af[mt], &bf[nt][2]);
                        mma_f16(acc_z[mt][2 * nt],     af[mt], &bz[nt][0]);
                        mma_f16(acc_z[mt][2 * nt + 1], af[mt], &bz[nt][2]);
                    }
            }
        } else {
#pragma unroll
            for (int s = 0; s < 4; s++) {
                uint32_t af[2][4], bf[2][4];
                ldsm4(af[0], sL + a_base + s * 32);
                ldsm4(af[1], sL + a_base + 16 * LDA + s * 32);
#pragma unroll
                for (int nt = 0; nt < 2; nt++)
                    ldsm4t(bf[nt], sB0 + b_base + s * 16 * LDB + nt * 32);
#pragma unroll
                for (int mt = 0; mt < 2; mt++)
#pragma unroll
                    for (int nt = 0; nt < 2; nt++) {
                        mma_f16(acc_o[mt][2 * nt],     af[mt], &bf[nt][0]);
                        mma_f16(acc_o[mt][2 * nt + 1], af[mt], &bf[nt][2]);
                    }
            }
        }

        // pipeline barrier: LHS(c+1) must be complete; B(c+1) STS visible
        if (c < 11) {
            if (c == 10) cpa_wait0(); else cpa_wait1();
            __syncthreads();
        }

        // rotate LHS slot for next iteration
        sL = (sL == L0) ? L1 : (sL == L1) ? L2 : L0;
    }

    // ---- epilogue: zz = hsig(C_o + b_o) * tanh(C_z + b_z); z += zz ----------
    const float* bo = freqb + (size_t)k * 256;
    const float* bz = freqb + (size_t)(256 + k) * 256;
#pragma unroll
    for (int mt = 0; mt < 2; mt++)
#pragma unroll
        for (int j = 0; j < 4; j++)
#pragma unroll
            for (int r = 0; r < 4; r++) {
                const int b = wm * 32 + mt * 16 + (l >> 2) + (r >> 1) * 8;
                const int v = v0 + wn * 32 + j * 8 + (l & 3) * 2 + (r & 1);
                const float o = hsig(acc_o[mt][j][r] + __ldg(bo + v));
                const float zz = o * tanhf(acc_z[mt][j][r] + __ldg(bz + v));
                atomicAdd(&z_out[b * 256 + v], zz);
            }
}

// ============================================================================
// launch
// ============================================================================
extern "C" void kernel_launch(void* const* d_in, const int* in_sizes, int n_in,
                              void* d_out, int out_size)
{
    const float* x        = (const float*)d_in[0];
    const float* t        = (const float*)d_in[1];
    const float* z_prev   = (const float*)d_in[2];
    const float* Im_prev  = (const float*)d_in[3];
    const float* Re_prev  = (const float*)d_in[4];
    const float* omg_prev = (const float*)d_in[5];
    const float* kern     = (const float*)d_in[6];
    const float* recur    = (const float*)d_in[7];
    const float* freq_k   = (const float*)d_in[8];
    const float* freq_ki  = (const float*)d_in[9];
    const float* bias     = (const float*)d_in[10];
    const float* freqb    = (const float*)d_in[11];

    float* out     = (float*)d_out;
    float* z_out   = out;
    float* im_out  = out + 32768;
    float* re_out  = out + 32768 + 8388608;
    float* omg_out = out + 32768 + 2 * 8388608;

    static int smem_set = 0;
    if (!smem_set) {
        cudaFuncSetAttribute(k_freq_mma, cudaFuncAttributeMaxDynamicSharedMemorySize, SMEM_TOT);
        smem_set = 1;
    }

    cudaMemsetAsync(z_out, 0, 32768 * sizeof(float), 0);
    k_gates_gemm<<<dim3(20, 4), 256>>>(x, z_prev, kern, recur, bias);
    k_gates_ew<<<128, 256>>>(x, z_prev, omg_prev, t, omg_out);
    k_reim<<<dim3(4, 4, 128), 256>>>(Re_prev, Im_prev, im_out, re_out);
    k_freq_mma<<<dim3(4, 256), 256, SMEM_TOT>>>(freq_k, freq_ki, freqb, z_out);
}